// round 1
// baseline (speedup 1.0000x reference)
#include <cuda_runtime.h>

#define BATCH 384
#define FEAT  256
#define NUM_ID 48
#define GROUP  8
#define RPB    4                 // rows per block in rank kernel (divides GROUP)
#define NBLK  (BATCH / RPB)      // 96

// Scratch in device globals (no allocations allowed).
__device__ float g_pn[BATCH * FEAT];     // normalized preds, row-major
__device__ float g_gnT[FEAT * BATCH];    // normalized gallery, TRANSPOSED [k][j]
__device__ float g_ginv[BATCH];          // 1/max(||g_j||, eps)
__device__ float g_partial[NBLK];        // per-block partial sums

// ---------------------------------------------------------------------------
// Kernel 1: row norms. Blocks 0..383 normalize preds rows and write g_pn.
// Blocks 384..767 compute gallery inverse norms only (transpose kernel scales).
// ---------------------------------------------------------------------------
__global__ void norm_kernel(const float* __restrict__ preds,
                            const float* __restrict__ gallery) {
    int row = blockIdx.x;
    int t   = threadIdx.x;            // 0..255
    bool isP = (row < BATCH);
    const float* src = isP ? (preds + row * FEAT)
                           : (gallery + (row - BATCH) * FEAT);
    float x  = src[t];
    float ss = x * x;
    __shared__ float wsum[8];
    #pragma unroll
    for (int off = 16; off > 0; off >>= 1)
        ss += __shfl_down_sync(0xffffffffu, ss, off);
    if ((t & 31) == 0) wsum[t >> 5] = ss;
    __syncthreads();
    float tot = wsum[0] + wsum[1] + wsum[2] + wsum[3]
              + wsum[4] + wsum[5] + wsum[6] + wsum[7];
    float inv = 1.0f / fmaxf(sqrtf(tot), 1e-12f);
    if (isP) {
        g_pn[row * FEAT + t] = x * inv;
    } else if (t == 0) {
        g_ginv[row - BATCH] = inv;
    }
}

// ---------------------------------------------------------------------------
// Kernel 2: normalized transpose of gallery: g_gnT[k][j] = g[j][k] * ginv[j].
// 32x32 smem tiles, coalesced on both sides.
// ---------------------------------------------------------------------------
__global__ void transpose_kernel(const float* __restrict__ gallery) {
    __shared__ float tile[32][33];
    int j0 = blockIdx.x * 32;         // gallery row tile  (384/32 = 12)
    int k0 = blockIdx.y * 32;         // feature tile      (256/32 = 8)
    int tx = threadIdx.x, ty = threadIdx.y;
    int j = j0 + ty, k = k0 + tx;
    tile[ty][tx] = gallery[j * FEAT + k] * g_ginv[j];
    __syncthreads();
    g_gnT[(k0 + ty) * BATCH + (j0 + tx)] = tile[tx][ty];
}

// ---------------------------------------------------------------------------
// Kernel 3: fused sim-row + rank kernel.
// Block handles RPB=4 consecutive rows i (all in one identity n = base/GROUP).
// Phase A: S[r][j] = pn[i_r] . gn[j]  for all j (coalesced gnT reads).
// Phase B: for each row, rank sums over the 8 diagonal-block columns.
// ---------------------------------------------------------------------------
__global__ __launch_bounds__(BATCH) void rank_kernel() {
    __shared__ float sp[RPB][FEAT];       // 4 KB
    __shared__ float S[RPB][BATCH];       // 6 KB
    __shared__ float wp[12][8];           // per-warp partials
    __shared__ float sratio[8];

    int tid  = threadIdx.x;               // 0..383
    int base = blockIdx.x * RPB;
    int warp = tid >> 5, lane = tid & 31;

    for (int idx = tid; idx < RPB * FEAT; idx += BATCH)
        ((float*)sp)[idx] = g_pn[base * FEAT + idx];
    __syncthreads();

    // ---- Phase A: 4 simultaneous GEMV rows ----
    float a0 = 0.f, a1 = 0.f, a2 = 0.f, a3 = 0.f;
    #pragma unroll 4
    for (int k = 0; k < FEAT; k += 4) {
        float4 p0 = *(const float4*)&sp[0][k];
        float4 p1 = *(const float4*)&sp[1][k];
        float4 p2 = *(const float4*)&sp[2][k];
        float4 p3 = *(const float4*)&sp[3][k];
        float gv0 = g_gnT[(k + 0) * BATCH + tid];
        float gv1 = g_gnT[(k + 1) * BATCH + tid];
        float gv2 = g_gnT[(k + 2) * BATCH + tid];
        float gv3 = g_gnT[(k + 3) * BATCH + tid];
        a0 += p0.x * gv0 + p0.y * gv1 + p0.z * gv2 + p0.w * gv3;
        a1 += p1.x * gv0 + p1.y * gv1 + p1.z * gv2 + p1.w * gv3;
        a2 += p2.x * gv0 + p2.y * gv1 + p2.z * gv2 + p2.w * gv3;
        a3 += p3.x * gv0 + p3.y * gv1 + p3.z * gv2 + p3.w * gv3;
    }
    S[0][tid] = a0; S[1][tid] = a1; S[2][tid] = a2; S[3][tid] = a3;
    __syncthreads();

    // ---- Phase B: rank sums ----
    int n = base / GROUP;                 // identity for all RPB rows
    float blocktotal = 0.f;               // valid on thread 0

    for (int r = 0; r < RPB; r++) {
        float dv[8];
        #pragma unroll
        for (int b = 0; b < 8; b++) dv[b] = S[r][n * GROUP + b];  // broadcast LDS
        float sval = S[r][tid];

        // sigmoid((dv[b]-sval)*100) == sigma((S[k]-S[jb])/temp), k = tid
        float sg[8];
        #pragma unroll
        for (int b = 0; b < 8; b++) {
            float e = fminf(fmaxf((dv[b] - sval) * 100.0f, -50.0f), 50.0f);
            sg[b] = __fdividef(1.0f, 1.0f + __expf(e));
        }
        // deterministic warp reduce (fixed order)
        #pragma unroll
        for (int b = 0; b < 8; b++) {
            #pragma unroll
            for (int off = 16; off > 0; off >>= 1)
                sg[b] += __shfl_down_sync(0xffffffffu, sg[b], off);
        }
        if (lane == 0) {
            #pragma unroll
            for (int b = 0; b < 8; b++) wp[warp][b] = sg[b];
        }
        __syncthreads();

        if (tid < 8) {
            int b = tid;
            float allrk = 0.f;
            #pragma unroll
            for (int w = 0; w < 12; w++) allrk += wp[w][b];
            float posrk = 0.f;
            #pragma unroll
            for (int c = 0; c < 8; c++) {
                float e = fminf(fmaxf((dv[b] - dv[c]) * 100.0f, -50.0f), 50.0f);
                posrk += __fdividef(1.0f, 1.0f + __expf(e));
            }
            sratio[b] = __fdividef(posrk, allrk);
        }
        __syncthreads();
        if (tid == 0) {
            float rsum = 0.f;
            #pragma unroll
            for (int b = 0; b < 8; b++) rsum += sratio[b];
            blocktotal += rsum;
        }
        __syncthreads();                  // wp/sratio reused next r
    }
    if (tid == 0) g_partial[blockIdx.x] = blocktotal;
}

// ---------------------------------------------------------------------------
// Kernel 4: final deterministic reduction, out = 1 - sum/(GROUP*BATCH)
// ---------------------------------------------------------------------------
__global__ void final_kernel(float* __restrict__ out) {
    __shared__ float w[4];
    int t = threadIdx.x;                  // 128 threads
    float v = (t < NBLK) ? g_partial[t] : 0.0f;
    #pragma unroll
    for (int off = 16; off > 0; off >>= 1)
        v += __shfl_down_sync(0xffffffffu, v, off);
    if ((t & 31) == 0) w[t >> 5] = v;
    __syncthreads();
    if (t == 0) {
        float tot = w[0] + w[1] + w[2] + w[3];
        out[0] = 1.0f - tot / (float)(GROUP * BATCH);
    }
}

extern "C" void kernel_launch(void* const* d_in, const int* in_sizes, int n_in,
                              void* d_out, int out_size) {
    const float* preds   = (const float*)d_in[0];
    const float* gallery = (const float*)d_in[1];
    float* out = (float*)d_out;

    norm_kernel<<<2 * BATCH, FEAT>>>(preds, gallery);
    transpose_kernel<<<dim3(BATCH / 32, FEAT / 32), dim3(32, 32)>>>(gallery);
    rank_kernel<<<NBLK, BATCH>>>();
    final_kernel<<<1, 128>>>(out);
}

// round 2
// speedup vs baseline: 1.3007x; 1.3007x over previous
#include <cuda_runtime.h>

#define BATCH 384
#define FEAT  256
#define NUM_ID 48
#define GROUP  8
#define RPB    4                 // rows per block (divides GROUP)
#define NBLK  (BATCH / RPB)      // 96 blocks <= 148 SMs -> all resident, spin barrier safe

// Scratch in device globals (no allocations allowed).
__device__ float g_gnT[FEAT * BATCH];       // normalized gallery, transposed [k][j]
__device__ float g_partial[NBLK];
__device__ unsigned g_bar  = 0;             // grid barrier arrival counter
__device__ unsigned g_done = 0;             // completion counter (last block reduces)

__global__ __launch_bounds__(BATCH, 1) void smoothap_kernel(
        const float* __restrict__ preds,
        const float* __restrict__ gallery,
        float* __restrict__ out) {
    __shared__ float sp[RPB][FEAT];         // this block's normalized pred rows (4 KB)
    __shared__ float S[RPB][BATCH];         // sims; first 4 KB reused as gallery staging (6 KB)
    __shared__ float inv8[8];               // 4 pred + 4 gallery inverse norms
    __shared__ float wp[12][RPB][8];        // per-warp rank partials (1.5 KB)
    __shared__ float wfin[3];
    __shared__ unsigned islast;

    int tid  = threadIdx.x;                 // 0..383
    int warp = tid >> 5, lane = tid & 31;
    int base = blockIdx.x * RPB;            // first row this block owns

    float* spf = &sp[0][0];
    float* sgf = &S[0][0];                  // gallery staging [4][256], aliases S

    // ---------------- Phase 0: load + normalize ----------------
    for (int idx = tid; idx < RPB * FEAT; idx += BATCH) {
        spf[idx] = preds  [base * FEAT + idx];
        sgf[idx] = gallery[base * FEAT + idx];
    }
    __syncthreads();

    if (warp < 8) {                         // warps 0-3: pred rows, 4-7: gallery rows
        int r = warp & 3;
        const float* row = (warp < 4) ? &sp[0][0] + r * FEAT : sgf + r * FEAT;
        float ss = 0.f;
        #pragma unroll
        for (int i = 0; i < FEAT / 32; i++) {
            float v = row[lane + 32 * i];
            ss += v * v;
        }
        #pragma unroll
        for (int off = 16; off > 0; off >>= 1)
            ss += __shfl_down_sync(0xffffffffu, ss, off);
        if (lane == 0) inv8[warp] = 1.0f / fmaxf(sqrtf(ss), 1e-12f);
    }
    __syncthreads();

    // scale pred rows in smem; write gallery rows transposed+normalized to global
    for (int idx = tid; idx < RPB * FEAT; idx += BATCH) {
        int r = idx >> 8, k = idx & 255;
        spf[idx] *= inv8[r];
        g_gnT[k * BATCH + base + r] = sgf[idx] * inv8[4 + r];
    }
    __syncthreads();

    // ---------------- Grid barrier ----------------
    if (tid == 0) {
        __threadfence();
        atomicAdd(&g_bar, 1u);
        while (atomicAdd(&g_bar, 0u) < (unsigned)NBLK) __nanosleep(64);
    }
    __syncthreads();

    // ---------------- Phase A: 4-row GEMV over all 384 columns ----------------
    float a0 = 0.f, a1 = 0.f, a2 = 0.f, a3 = 0.f;
    #pragma unroll 4
    for (int k = 0; k < FEAT; k += 4) {
        float4 p0 = *(const float4*)&sp[0][k];
        float4 p1 = *(const float4*)&sp[1][k];
        float4 p2 = *(const float4*)&sp[2][k];
        float4 p3 = *(const float4*)&sp[3][k];
        float gv0 = __ldcg(&g_gnT[(k + 0) * BATCH + tid]);
        float gv1 = __ldcg(&g_gnT[(k + 1) * BATCH + tid]);
        float gv2 = __ldcg(&g_gnT[(k + 2) * BATCH + tid]);
        float gv3 = __ldcg(&g_gnT[(k + 3) * BATCH + tid]);
        a0 += p0.x * gv0 + p0.y * gv1 + p0.z * gv2 + p0.w * gv3;
        a1 += p1.x * gv0 + p1.y * gv1 + p1.z * gv2 + p1.w * gv3;
        a2 += p2.x * gv0 + p2.y * gv1 + p2.z * gv2 + p2.w * gv3;
        a3 += p3.x * gv0 + p3.y * gv1 + p3.z * gv2 + p3.w * gv3;
    }
    __syncthreads();                        // staging region (S) no longer needed
    S[0][tid] = a0; S[1][tid] = a1; S[2][tid] = a2; S[3][tid] = a3;
    __syncthreads();

    // ---------------- Phase B: rank sums ----------------
    int n8 = (base >> 3) << 3;              // start column of the diagonal block

    #pragma unroll
    for (int r = 0; r < RPB; r++) {
        float dv[8];
        #pragma unroll
        for (int b = 0; b < 8; b++) dv[b] = S[r][n8 + b];   // smem broadcast
        float sval = S[r][tid];
        float sg[8];
        #pragma unroll
        for (int b = 0; b < 8; b++) {
            float e = fminf(fmaxf((dv[b] - sval) * 100.0f, -50.0f), 50.0f);
            sg[b] = __fdividef(1.0f, 1.0f + __expf(e));
        }
        #pragma unroll
        for (int b = 0; b < 8; b++) {
            #pragma unroll
            for (int off = 16; off > 0; off >>= 1)
                sg[b] += __shfl_down_sync(0xffffffffu, sg[b], off);
        }
        if (lane == 0) {
            #pragma unroll
            for (int b = 0; b < 8; b++) wp[warp][r][b] = sg[b];
        }
    }
    __syncthreads();

    float btotal = 0.f;                     // valid on lane 0 of warp 0 after reduce
    if (tid < 32) {                         // warp 0: one thread per (r, b)
        int r = tid >> 3, b = tid & 7;
        float allrk = 0.f;
        #pragma unroll
        for (int w = 0; w < 12; w++) allrk += wp[w][r][b];
        float db = S[r][n8 + b];
        float posrk = 0.f;
        #pragma unroll
        for (int c = 0; c < 8; c++) {
            float e = fminf(fmaxf((db - S[r][n8 + c]) * 100.0f, -50.0f), 50.0f);
            posrk += __fdividef(1.0f, 1.0f + __expf(e));
        }
        float ratio = __fdividef(posrk, allrk);
        #pragma unroll
        for (int off = 16; off > 0; off >>= 1)
            ratio += __shfl_down_sync(0xffffffffu, ratio, off);
        btotal = ratio;
    }
    if (tid == 0) {
        g_partial[blockIdx.x] = btotal;
        __threadfence();
        islast = (atomicAdd(&g_done, 1u) == (unsigned)(NBLK - 1)) ? 1u : 0u;
    }
    __syncthreads();

    // ---------------- Final reduction by the last block ----------------
    if (islast) {
        float v = (tid < NBLK) ? __ldcg(&g_partial[tid]) : 0.0f;
        if (tid < 96) {
            #pragma unroll
            for (int off = 16; off > 0; off >>= 1)
                v += __shfl_down_sync(0xffffffffu, v, off);
            if (lane == 0) wfin[warp] = v;
        }
        __syncthreads();
        if (tid == 0) {
            float tot = wfin[0] + wfin[1] + wfin[2];
            out[0] = 1.0f - tot / (float)(GROUP * BATCH);
            g_bar  = 0;                     // reset for next graph replay
            g_done = 0;
        }
    }
}

extern "C" void kernel_launch(void* const* d_in, const int* in_sizes, int n_in,
                              void* d_out, int out_size) {
    const float* preds   = (const float*)d_in[0];
    const float* gallery = (const float*)d_in[1];
    float* out = (float*)d_out;
    smoothap_kernel<<<NBLK, BATCH>>>(preds, gallery, out);
}

// round 5
// speedup vs baseline: 1.6042x; 1.2333x over previous
#include <cuda_runtime.h>
#include <cstdint>

#define BATCH 384
#define FEAT  256
#define GROUP 8
#define RPB   4                  // pred rows per block
#define NBLK  (BATCH / RPB)      // 96 blocks <= 148 SMs -> spin barrier safe
#define NT    768                // threads per block: 8 k-eighths x 96 col-groups

// Scratch in device globals (no allocations allowed).
__device__ float g_gnT[FEAT * BATCH];       // normalized gallery, transposed [k][j]
__device__ float g_partial[NBLK];
__device__ unsigned g_bar  = 0;
__device__ unsigned g_done = 0;

__device__ __forceinline__ uint64_t pack2(float lo, float hi) {
    uint64_t r; asm("mov.b64 %0, {%1, %2};" : "=l"(r) : "f"(lo), "f"(hi)); return r;
}
__device__ __forceinline__ void unpack2(uint64_t v, float& lo, float& hi) {
    asm("mov.b64 {%0, %1}, %2;" : "=f"(lo), "=f"(hi) : "l"(v));
}
__device__ __forceinline__ void fma2(uint64_t& acc, uint64_t a, uint64_t b) {
    asm("fma.rn.f32x2 %0, %1, %2, %0;" : "+l"(acc) : "l"(a), "l"(b));
}
__device__ __forceinline__ float sigm(float d) {   // 1/(1+exp(clip(d*100)))
    float e = fminf(fmaxf(d * 100.0f, -50.0f), 50.0f);
    return __fdividef(1.0f, 1.0f + __expf(e));
}

__global__ __launch_bounds__(NT, 1) void smoothap_kernel(
        const float* __restrict__ preds,
        const float* __restrict__ gallery,
        float* __restrict__ out) {
    __shared__ uint64_t sp01[FEAT];          // packed {p0,p1}[k] (2 KB)
    __shared__ uint64_t sp23[FEAT];          // packed {p2,p3}[k] (2 KB)
    __shared__ float part[4][RPB][BATCH];    // split-K partials / staging (24 KB)
    __shared__ float S[RPB][BATCH];          // sims (6 KB)
    __shared__ float inv8[8];
    __shared__ float wp[24][2][8];           // per-warp rank partials (1.5 KB)
    __shared__ float wfin[3];
    __shared__ unsigned islast;

    int tid  = threadIdx.x;
    int warp = tid >> 5, lane = tid & 31;
    int base = blockIdx.x * RPB;

    // ---------------- Phase 0: stage + normalize ----------------
    float* stage = &part[0][0][0];           // [0..1023] preds, [1024..2047] gallery
    for (int idx = tid; idx < 2 * RPB * FEAT; idx += NT)
        stage[idx] = (idx < RPB * FEAT) ? preds[base * FEAT + idx]
                                        : gallery[base * FEAT + idx - RPB * FEAT];
    __syncthreads();

    if (warp < 8) {                          // warps 0-3 pred rows, 4-7 gallery rows
        const float* row = stage + warp * FEAT;
        float ss = 0.f;
        #pragma unroll
        for (int i = 0; i < FEAT / 32; i++) { float v = row[lane + 32 * i]; ss += v * v; }
        #pragma unroll
        for (int off = 16; off > 0; off >>= 1)
            ss += __shfl_down_sync(0xffffffffu, ss, off);
        if (lane == 0) inv8[warp] = 1.0f / fmaxf(sqrtf(ss), 1e-12f);
    }
    __syncthreads();

    if (tid < FEAT) {                        // pack normalized pred row-pairs
        int k = tid;
        sp01[k] = pack2(stage[0 * FEAT + k] * inv8[0], stage[1 * FEAT + k] * inv8[1]);
        sp23[k] = pack2(stage[2 * FEAT + k] * inv8[2], stage[3 * FEAT + k] * inv8[3]);
    }
    for (int idx = tid; idx < RPB * FEAT; idx += NT) {  // publish gallery transposed
        int r = idx >> 8, k = idx & 255;
        g_gnT[k * BATCH + base + r] = stage[RPB * FEAT + idx] * inv8[4 + r];
    }
    __syncthreads();

    // ---------------- Grid barrier (all 96 blocks wave-1 resident) ----------
    if (tid == 0) {
        __threadfence();
        atomicAdd(&g_bar, 1u);
        while (atomicAdd(&g_bar, 0u) < (unsigned)NBLK) __nanosleep(32);
    }
    __syncthreads();

    // ---------------- Phase A: split-K GEMV, f32x2 packed, float4 loads ------
    int c4 = (tid % 96) * 4;                 // this thread's 4 columns
    int q  = tid / 96;                       // k-eighth: k in [32q, 32q+32)
    uint64_t acc[4][2];                      // [col][{r0,r1} / {r2,r3}]
    #pragma unroll
    for (int c = 0; c < 4; c++) { acc[c][0] = 0ull; acc[c][1] = 0ull; }

    const float4* gp = (const float4*)&g_gnT[(q * 32) * BATCH + c4];
    #pragma unroll 4
    for (int kk = 0; kk < 32; kk++) {
        int k = q * 32 + kk;
        float4 g = __ldcg(gp); gp += BATCH / 4;
        uint64_t p01 = sp01[k], p23 = sp23[k];
        uint64_t gg;
        gg = pack2(g.x, g.x); fma2(acc[0][0], p01, gg); fma2(acc[0][1], p23, gg);
        gg = pack2(g.y, g.y); fma2(acc[1][0], p01, gg); fma2(acc[1][1], p23, gg);
        gg = pack2(g.z, g.z); fma2(acc[2][0], p01, gg); fma2(acc[2][1], p23, gg);
        gg = pack2(g.w, g.w); fma2(acc[3][0], p01, gg); fma2(acc[3][1], p23, gg);
    }

    float a[RPB][4];                         // [row][col]
    #pragma unroll
    for (int c = 0; c < 4; c++) {
        unpack2(acc[c][0], a[0][c], a[1][c]);
        unpack2(acc[c][1], a[2][c], a[3][c]);
    }
    __syncthreads();                         // stage (aliases part) fully consumed

    // split-K reduction tree (deterministic fixed order): 8 -> 4 -> 2 -> 1
    if (q >= 4) {
        #pragma unroll
        for (int r = 0; r < RPB; r++)
            *(float4*)&part[q - 4][r][c4] = make_float4(a[r][0], a[r][1], a[r][2], a[r][3]);
    }
    __syncthreads();
    if (q < 4) {
        #pragma unroll
        for (int r = 0; r < RPB; r++) {
            float4 v = *(const float4*)&part[q][r][c4];
            a[r][0] += v.x; a[r][1] += v.y; a[r][2] += v.z; a[r][3] += v.w;
        }
    }
    __syncthreads();
    if (q >= 2 && q < 4) {
        #pragma unroll
        for (int r = 0; r < RPB; r++)
            *(float4*)&part[q - 2][r][c4] = make_float4(a[r][0], a[r][1], a[r][2], a[r][3]);
    }
    __syncthreads();
    if (q < 2) {
        #pragma unroll
        for (int r = 0; r < RPB; r++) {
            float4 v = *(const float4*)&part[q][r][c4];
            a[r][0] += v.x; a[r][1] += v.y; a[r][2] += v.z; a[r][3] += v.w;
        }
    }
    __syncthreads();
    if (q == 1) {
        #pragma unroll
        for (int r = 0; r < RPB; r++)
            *(float4*)&part[0][r][c4] = make_float4(a[r][0], a[r][1], a[r][2], a[r][3]);
    }
    __syncthreads();
    if (q == 0) {
        #pragma unroll
        for (int r = 0; r < RPB; r++) {
            float4 v = *(const float4*)&part[0][r][c4];
            *(float4*)&S[r][c4] = make_float4(a[r][0] + v.x, a[r][1] + v.y,
                                              a[r][2] + v.z, a[r][3] + v.w);
        }
    }
    __syncthreads();

    // ---------------- Phase B: rank sums (2 rows per thread) ----------------
    int col  = tid % BATCH;
    int half = tid / BATCH;                  // 0 -> rows {0,1}, 1 -> rows {2,3}
    int n8   = base & ~(GROUP - 1);          // diagonal-block start column

    #pragma unroll
    for (int rr = 0; rr < 2; rr++) {
        int r = half * 2 + rr;
        float sval = S[r][col];
        float sg[8];
        #pragma unroll
        for (int b = 0; b < 8; b++) sg[b] = sigm(S[r][n8 + b] - sval);
        #pragma unroll
        for (int b = 0; b < 8; b++) {
            #pragma unroll
            for (int off = 16; off > 0; off >>= 1)
                sg[b] += __shfl_down_sync(0xffffffffu, sg[b], off);
        }
        if (lane == 0) {
            #pragma unroll
            for (int b = 0; b < 8; b++) wp[warp][rr][b] = sg[b];
        }
    }
    __syncthreads();

    float btotal = 0.f;
    if (tid < 32) {                          // one thread per (row, b)
        int r = tid >> 3, b = tid & 7;
        int w0 = (r >> 1) * 12, rr = r & 1;  // rows 0,1 -> warps 0-11; rows 2,3 -> 12-23
        float allrk = 0.f;
        #pragma unroll
        for (int w = 0; w < 12; w++) allrk += wp[w0 + w][rr][b];
        float db = S[r][n8 + b];
        float posrk = 0.f;
        #pragma unroll
        for (int c = 0; c < 8; c++) posrk += sigm(db - S[r][n8 + c]);
        float ratio = __fdividef(posrk, allrk);
        #pragma unroll
        for (int off = 16; off > 0; off >>= 1)
            ratio += __shfl_down_sync(0xffffffffu, ratio, off);
        btotal = ratio;
    }
    if (tid == 0) {
        g_partial[blockIdx.x] = btotal;
        __threadfence();
        islast = (atomicAdd(&g_done, 1u) == (unsigned)(NBLK - 1)) ? 1u : 0u;
    }
    __syncthreads();

    // ---------------- Final reduction by the last-done block ----------------
    if (islast) {
        if (tid < 96) {
            float v = __ldcg(&g_partial[tid]);
            #pragma unroll
            for (int off = 16; off > 0; off >>= 1)
                v += __shfl_down_sync(0xffffffffu, v, off);
            if (lane == 0) wfin[warp] = v;
        }
        __syncthreads();
        if (tid == 0) {
            float tot = wfin[0] + wfin[1] + wfin[2];
            out[0] = 1.0f - tot / (float)(GROUP * BATCH);
            g_bar  = 0;                      // reset for next graph replay
            g_done = 0;
        }
    }
}

extern "C" void kernel_launch(void* const* d_in, const int* in_sizes, int n_in,
                              void* d_out, int out_size) {
    const float* preds   = (const float*)d_in[0];
    const float* gallery = (const float*)d_in[1];
    float* out = (float*)d_out;
    smoothap_kernel<<<NBLK, NT>>>(preds, gallery, out);
}